// round 15
// baseline (speedup 1.0000x reference)
#include <cuda_runtime.h>
#include <cstdint>

// B=8, C=4, H=W=1024, PATCH=16, DOWN=4 -> L=4096 (64x64 patches), M=256.
// att_gt[b,c,l,m] = (1/4096) * sum_{k: class(b,l,k)==c} cnt[b,c, pix(m,k)]
//   cnt in [0,16]. Loss = mean((att - att_gt)^2) over 33.5M elements.
// target is int32 on disk. Scalar smem path; V stored as NIBBLES (2 m / byte)
// when no 4x4 block saturates at 16 (checked exactly via g_sat; u8 fallback).

// ---------------- device scratch ----------------
static __device__ __align__(16) uint8_t g_T[8u * 4096u * 256u];      // [b][l][k] class
static __device__ __align__(16) uint8_t g_V[8u * 4u * 256u * 256u];  // [b][c][k][m] u8
static __device__ __align__(16) uint8_t g_Vn[8u * 4u * 256u * 128u]; // [b][c][k][m/2] nib
static __device__ __align__(16) uint8_t g_list[8u * 4096u * 256u];   // [b][l] k's by class
static __device__ ushort4  g_cnt[8u * 4096u];
static __device__ uint32_t g_sat[32];
static __device__ double   g_part[256];

// ---------------- kernel 0: zero saturation flags ------------------------
__global__ void k_init() { if (threadIdx.x < 32) g_sat[threadIdx.x] = 0u; }

// ---------------- kernel 1: target -> class bytes g_T[b][l][k] ----------
__global__ void k_compact(const int* __restrict__ tgt) {
    int t = threadIdx.x;
    int py = blockIdx.x & 63, b = blockIdx.x >> 6;
#pragma unroll 4
    for (int ky = 0; ky < 16; ky++) {
        int4 q = *reinterpret_cast<const int4*>(
            tgt + ((size_t)b << 20) + (size_t)(py * 16 + ky) * 1024 + t * 4);
        uint32_t w = (uint32_t)(q.x & 255) | ((uint32_t)(q.y & 255) << 8)
                   | ((uint32_t)(q.z & 255) << 16) | ((uint32_t)(q.w & 255) << 24);
        size_t off = ((size_t)b * 4096 + py * 64 + (t >> 2)) * 256
                   + ky * 16 + (t & 3) * 4;
        *reinterpret_cast<uint32_t*>(g_T + off) = w;
    }
}

// ---------------- kernel 2: pooled counts -> g_V u8 + g_Vn nibble --------
// block = (b, pooled row Y); thread X = pooled col. Reads 16 class bytes
// from g_T (4 u32), counts via vcmpeq4+dp4a, stages, writes both tables.
__global__ void k_pool() {
    __shared__ __align__(16) uint8_t stage[4][16][16];   // [c][kx][mx]
    int X = threadIdx.x;
    int Y = blockIdx.x & 255, b = blockIdx.x >> 8;
    int py = Y >> 2, a = Y & 3, px = X >> 2, bb = X & 3;
    const uint8_t* row = g_T + ((size_t)(b * 4096 + py * 64 + px) << 8);
    uint32_t w0 = *(const uint32_t*)(row + (4 * a + 0) * 16 + 4 * bb);
    uint32_t w1 = *(const uint32_t*)(row + (4 * a + 1) * 16 + 4 * bb);
    uint32_t w2 = *(const uint32_t*)(row + (4 * a + 2) * 16 + 4 * bb);
    uint32_t w3 = *(const uint32_t*)(row + (4 * a + 3) * 16 + 4 * bb);
    int kx = X & 15, mx = X >> 4;
#pragma unroll
    for (int c = 0; c < 4; c++) {
        uint32_t cc = 0x01010101u * (uint32_t)c;
        int s = __dp4a((int)(__vcmpeq4(w0, cc) & 0x01010101u), 0x01010101, 0);
        s = __dp4a((int)(__vcmpeq4(w1, cc) & 0x01010101u), 0x01010101, s);
        s = __dp4a((int)(__vcmpeq4(w2, cc) & 0x01010101u), 0x01010101, s);
        s = __dp4a((int)(__vcmpeq4(w3, cc) & 0x01010101u), 0x01010101, s);
        stage[c][kx][mx] = (uint8_t)s;
        if (s >= 16) atomicOr(&g_sat[b * 4 + c], 1u);   // saturation -> fallback
    }
    __syncthreads();
    if (X < 64) {
        int c = X >> 4, kxe = X & 15;
        int kk = (Y & 15) * 16 + kxe;          // k row index
        int mbase = (Y >> 4) << 4;
        size_t bc = (size_t)b * 4 + c;
        uint4 v = *reinterpret_cast<const uint4*>(&stage[c][kxe][0]);
        *reinterpret_cast<uint4*>(g_V + (bc << 16) + (size_t)kk * 256 + mbase) = v;
        // nibble pack: byte j = cnt(m=2j) | cnt(m=2j+1)<<4  (capped to 15)
        uint32_t x0 = __vminu4(v.x, 0x0F0F0F0Fu), y0 = __vminu4(v.y, 0x0F0F0F0Fu);
        uint32_t x1 = __vminu4(v.z, 0x0F0F0F0Fu), y1 = __vminu4(v.w, 0x0F0F0F0Fu);
        uint32_t p0 = x0 | (x0 >> 4), p1 = y0 | (y0 >> 4);
        uint32_t p2 = x1 | (x1 >> 4), p3 = y1 | (y1 >> 4);
        uint2 nb;
        nb.x = __byte_perm(p0, p1, 0x6420);
        nb.y = __byte_perm(p2, p3, 0x6420);
        *reinterpret_cast<uint2*>(g_Vn + (bc << 15) + (size_t)kk * 128
                                  + (mbase >> 1)) = nb;
    }
}

// ---------------- kernel 3: per-(b,l) counting sort of k by class -------
__global__ void k_lists() {
    __shared__ uint8_t sc[8 * 256];
    int warp = threadIdx.x >> 5, lane = threadIdx.x & 31;
    int gw = blockIdx.x * 8 + warp;                  // b*4096 + l
    ((uint64_t*)(sc + warp * 256))[lane] =
        ((const uint64_t*)(g_T + ((size_t)gw << 8)))[lane];
    __syncwarp();
    const uint8_t* cw = sc + warp * 256;
    int t0 = 0, t1 = 0, t2 = 0, t3 = 0;
#pragma unroll
    for (int r = 0; r < 8; r++) {
        int c = cw[r * 32 + lane];
        t0 += __popc(__ballot_sync(0xffffffffu, c == 0));
        t1 += __popc(__ballot_sync(0xffffffffu, c == 1));
        t2 += __popc(__ballot_sync(0xffffffffu, c == 2));
        t3 += __popc(__ballot_sync(0xffffffffu, c == 3));
    }
    int b0 = 0, b1 = t0, b2 = t0 + t1, b3 = t0 + t1 + t2;
    uint8_t* out = g_list + ((size_t)gw << 8);
    unsigned lt = (1u << lane) - 1u;
#pragma unroll
    for (int r = 0; r < 8; r++) {
        int k = r * 32 + lane;
        int c = cw[k];
        unsigned m0 = __ballot_sync(0xffffffffu, c == 0);
        unsigned m1 = __ballot_sync(0xffffffffu, c == 1);
        unsigned m2 = __ballot_sync(0xffffffffu, c == 2);
        unsigned m3 = __ballot_sync(0xffffffffu, c == 3);
        int pos = (c == 0) ? b0 + __popc(m0 & lt)
                : (c == 1) ? b1 + __popc(m1 & lt)
                : (c == 2) ? b2 + __popc(m2 & lt)
                :            b3 + __popc(m3 & lt);
        out[pos] = (uint8_t)k;
        b0 += __popc(m0); b1 += __popc(m1); b2 += __popc(m2); b3 += __popc(m3);
    }
    if (lane == 0)
        g_cnt[gw] = make_ushort4((unsigned short)t0, (unsigned short)t1,
                                 (unsigned short)t2, (unsigned short)t3);
}

// ---------------- kernel 4: main accumulation + fused MSE ----------------
// grid (lg=8, c=4, b=8) = 256 blocks, 512 threads (16 warps). smem: nibble
// V slab 32KB + 16x256B lists. Warp owns one l per iter; lane owns 8 m via
// one LDS.32/k (2 nibble planes), u8-SIMD windows of 16 k, PRMT flush.
#define FLUSH_NIB(lo, hi)                                            \
    e0 += __byte_perm(lo, 0, 0x4140); e1 += __byte_perm(lo, 0, 0x4342); \
    o0 += __byte_perm(hi, 0, 0x4140); o1 += __byte_perm(hi, 0, 0x4342)

__global__ void __launch_bounds__(512, 2) k_main(const float* __restrict__ att) {
    extern __shared__ uint8_t sm[];
    uint8_t* Vn = sm;                       // 32768 B nibble slab
    uint8_t* Ls = sm + 32768;               // 16 warps * 256 B
    double*  wsum = (double*)(sm + 32768 + 4096);
    int b = blockIdx.z, c = blockIdx.y, lg = blockIdx.x;
    size_t bc = (size_t)b * 4 + c;
    uint32_t sat = g_sat[b * 4 + c];

    {   // load nibble slab (2048 uint4)
        const uint4* src = (const uint4*)(g_Vn + (bc << 15));
        uint4* dst = (uint4*)Vn;
        for (int i = threadIdx.x; i < 2048; i += 512) dst[i] = src[i];
    }
    __syncthreads();

    int warp = threadIdx.x >> 5, lane = threadIdx.x & 31;
    uint8_t* lw = Ls + warp * 256;
    const uint32_t* Vl = (const uint32_t*)Vn + lane;     // stride 32 u32 per k
    const uint32_t M = 0x0F0F0F0Fu;
    const float inv = 1.0f / 4096.0f;
    float s = 0.0f;

    for (int li = 0; li < 32; li++) {
        int l = (lg << 9) + (li << 4) + warp;
        size_t lbase = (size_t)b * 4096 + l;
        __syncwarp();
        ((uint64_t*)lw)[lane] = ((const uint64_t*)g_list)[lbase * 32 + lane];
        __syncwarp();
        ushort4 cn = g_cnt[lbase];
        int start = (c > 0 ? (int)cn.x : 0) + (c > 1 ? (int)cn.y : 0)
                  + (c > 2 ? (int)cn.z : 0);
        int n = (c == 0) ? (int)cn.x : (c == 1) ? (int)cn.y
              : (c == 2) ? (int)cn.z : (int)cn.w;

        const float4* ap = (const float4*)att
                         + ((bc * 4096 + l) << 6) + (lane << 1);
        float4 q0 = __ldg(ap);
        float4 q1 = __ldg(ap + 1);

        int p = start, e = start + n;
        if (!sat) {
            uint32_t e0 = 0, e1 = 0, o0 = 0, o1 = 0;
            {   // head to 4-alignment (<=3), own flush window
                uint32_t lo = 0, hi = 0;
                while ((p & 3) && p < e) {
                    int k = lw[p++];
                    uint32_t v = Vl[k << 5];
                    lo += v & M; hi += (v >> 4) & M;
                }
                FLUSH_NIB(lo, hi);
            }
            const uint32_t* wp = (const uint32_t*)lw;
            while (e - p >= 16) {           // 16-k windows: 16 adds <= 240
                uint32_t lo = 0, hi = 0;
#pragma unroll
                for (int g = 0; g < 4; g++) {
                    uint32_t i4 = wp[(p >> 2) + g];
                    uint32_t v0 = Vl[(i4 & 255u) << 5];
                    uint32_t v1 = Vl[((i4 >> 8) & 255u) << 5];
                    uint32_t v2 = Vl[((i4 >> 16) & 255u) << 5];
                    uint32_t v3 = Vl[(i4 >> 24) << 5];
                    lo += v0 & M; hi += (v0 >> 4) & M;
                    lo += v1 & M; hi += (v1 >> 4) & M;
                    lo += v2 & M; hi += (v2 >> 4) & M;
                    lo += v3 & M; hi += (v3 >> 4) & M;
                }
                FLUSH_NIB(lo, hi);
                p += 16;
            }
            {   // tail <=15
                uint32_t lo = 0, hi = 0;
                while (e - p >= 4) {
                    uint32_t i4 = wp[p >> 2];
                    uint32_t v0 = Vl[(i4 & 255u) << 5];
                    uint32_t v1 = Vl[((i4 >> 8) & 255u) << 5];
                    uint32_t v2 = Vl[((i4 >> 16) & 255u) << 5];
                    uint32_t v3 = Vl[(i4 >> 24) << 5];
                    lo += v0 & M; hi += (v0 >> 4) & M;
                    lo += v1 & M; hi += (v1 >> 4) & M;
                    lo += v2 & M; hi += (v2 >> 4) & M;
                    lo += v3 & M; hi += (v3 >> 4) & M;
                    p += 4;
                }
                while (p < e) {
                    int k = lw[p++];
                    uint32_t v = Vl[k << 5];
                    lo += v & M; hi += (v >> 4) & M;
                }
                FLUSH_NIB(lo, hi);
            }
            // MSE: m = 8*lane + j; even m in e*, odd m in o*
            float d;
            d = q0.x - (float)(e0 & 0xffffu) * inv; s += d * d;
            d = q0.y - (float)(o0 & 0xffffu) * inv; s += d * d;
            d = q0.z - (float)(e0 >> 16)     * inv; s += d * d;
            d = q0.w - (float)(o0 >> 16)     * inv; s += d * d;
            d = q1.x - (float)(e1 & 0xffffu) * inv; s += d * d;
            d = q1.y - (float)(o1 & 0xffffu) * inv; s += d * d;
            d = q1.z - (float)(e1 >> 16)     * inv; s += d * d;
            d = q1.w - (float)(o1 >> 16)     * inv; s += d * d;
        } else {
            // exact u8 fallback from global (saturated slab; ~never taken)
            uint32_t a0 = 0, a1 = 0, a2 = 0, a3 = 0;
            const uint8_t* gv = g_V + (bc << 16) + (lane << 3);
            for (; p < e; p++) {
                int k = lw[p];
                uint2 v = __ldg((const uint2*)(gv + (k << 8)));
                a0 += __byte_perm(v.x, 0, 0x4140); a1 += __byte_perm(v.x, 0, 0x4342);
                a2 += __byte_perm(v.y, 0, 0x4140); a3 += __byte_perm(v.y, 0, 0x4342);
            }
            float d;
            d = q0.x - (float)(a0 & 0xffffu) * inv; s += d * d;
            d = q0.y - (float)(a0 >> 16)     * inv; s += d * d;
            d = q0.z - (float)(a1 & 0xffffu) * inv; s += d * d;
            d = q0.w - (float)(a1 >> 16)     * inv; s += d * d;
            d = q1.x - (float)(a2 & 0xffffu) * inv; s += d * d;
            d = q1.y - (float)(a2 >> 16)     * inv; s += d * d;
            d = q1.z - (float)(a3 & 0xffffu) * inv; s += d * d;
            d = q1.w - (float)(a3 >> 16)     * inv; s += d * d;
        }
    }

    // deterministic block reduction
#pragma unroll
    for (int o = 16; o > 0; o >>= 1) s += __shfl_down_sync(0xffffffffu, s, o);
    if (lane == 0) wsum[warp] = (double)s;
    __syncthreads();
    if (threadIdx.x == 0) {
        double t = 0.0;
#pragma unroll
        for (int w = 0; w < 16; w++) t += wsum[w];
        g_part[((size_t)blockIdx.z * 4 + blockIdx.y) * 8 + blockIdx.x] = t;
    }
}

// ---------------- kernel 5: final deterministic reduction ----------------
__global__ void k_final(float* __restrict__ out) {
    __shared__ double sh[256];
    int t = threadIdx.x;
    sh[t] = g_part[t];
    __syncthreads();
#pragma unroll
    for (int o = 128; o > 0; o >>= 1) {
        if (t < o) sh[t] += sh[t + o];
        __syncthreads();
    }
    if (t == 0) out[0] = (float)(sh[0] / 33554432.0);
}

// ---------------- launch -------------------------------------------------
extern "C" void kernel_launch(void* const* d_in, const int* in_sizes, int n_in,
                              void* d_out, int out_size) {
    (void)in_sizes; (void)n_in; (void)out_size;
    // d_in[0] = pred (unused), d_in[1] = target int32, d_in[2] = attentions f32
    const int*   tgt = (const int*)d_in[1];
    const float* att = (const float*)d_in[2];
    float*       out = (float*)d_out;

    const int MAIN_SMEM = 32768 + 4096 + 16 * (int)sizeof(double);
    cudaFuncSetAttribute(k_main, cudaFuncAttributeMaxDynamicSharedMemorySize,
                         MAIN_SMEM);

    k_init<<<1, 32>>>();
    k_compact<<<512, 256>>>(tgt);
    k_pool<<<2048, 256>>>();
    k_lists<<<4096, 256>>>();
    k_main<<<dim3(8, 4, 8), 512, MAIN_SMEM>>>(att);
    k_final<<<1, 256>>>(out);
}